// round 8
// baseline (speedup 1.0000x reference)
#include <cuda_runtime.h>
#include <cstdint>

#define NN 100000
#define PP 250000
#define PPB 64
#define NTHREADS 256

__device__ float g_fd[NN * 16];   // degree-gate values, recomputed every call

// Packed Blackwell f32x2 ops (only reachable via inline PTX)
#define FMAX2(acc, a, b) \
    asm("fma.rn.f32x2 %0, %1, %2, %0;" : "+l"(acc) : "l"(a), "l"(b))
#define ADD2(acc, b) \
    asm("add.rn.f32x2 %0, %0, %1;" : "+l"(acc) : "l"(b))
#define PACK2(dst, src) \
    asm("mov.b64 %0, {%1, %1};" : "=l"(dst) : "r"(src))
#define RED4(ptr, a, b, c, d) \
    asm volatile("red.global.add.v4.f32 [%0], {%1,%2,%3,%4};" \
                 :: "l"(ptr), "f"(a), "f"(b), "f"(c), "f"(d) : "memory")

// ---------------------------------------------------------------------------
// Kernel 1: fd[n,c] = relu(degs[n]*W0 + b0) @ W1 + b1 into g_fd; zero d_out.
// ---------------------------------------------------------------------------
__global__ __launch_bounds__(256) void fd_pre_kernel(
    const float* __restrict__ degs,
    const float* __restrict__ W0, const float* __restrict__ b0,
    const float* __restrict__ W1, const float* __restrict__ b1,
    float* __restrict__ out)
{
    __shared__ float sw0[32], sb0[32];
    __shared__ ulonglong2 sw1v[128];
    __shared__ unsigned long long sb1p[8];

    int tid = threadIdx.x;
    if (tid < 32) { sw0[tid] = W0[tid]; sb0[tid] = b0[tid]; }
    if (tid < 128) sw1v[tid] = ((const ulonglong2*)W1)[tid];
    if (tid < 8)  sb1p[tid] = ((const unsigned long long*)b1)[tid];
    __syncthreads();

    int n = blockIdx.x * 256 + tid;
    if (n >= NN) return;

    unsigned long long acc[8];
    #pragma unroll
    for (int i = 0; i < 8; ++i) acc[i] = sb1p[i];

    float dg = degs[n];
    #pragma unroll
    for (int j = 0; j < 32; ++j) {
        float h = fmaxf(fmaf(dg, sw0[j], sb0[j]), 0.f);
        unsigned long long hh; PACK2(hh, __float_as_uint(h));
        const ulonglong2* wp = sw1v + j * 4;
        ulonglong2 wA = wp[0], wB = wp[1], wC = wp[2], wD = wp[3];
        FMAX2(acc[0], hh, wA.x); FMAX2(acc[1], hh, wA.y);
        FMAX2(acc[2], hh, wB.x); FMAX2(acc[3], hh, wB.y);
        FMAX2(acc[4], hh, wC.x); FMAX2(acc[5], hh, wC.y);
        FMAX2(acc[6], hh, wD.x); FMAX2(acc[7], hh, wD.y);
    }

    ulonglong2* fdv = (ulonglong2*)(g_fd + n * 16);
    fdv[0] = make_ulonglong2(acc[0], acc[1]);
    fdv[1] = make_ulonglong2(acc[2], acc[3]);
    fdv[2] = make_ulonglong2(acc[4], acc[5]);
    fdv[3] = make_ulonglong2(acc[6], acc[7]);

    float4 z = make_float4(0.f, 0.f, 0.f, 0.f);
    float4* ov = (float4*)(out + n * 16);
    ov[0] = z; ov[1] = z; ov[2] = z; ov[3] = z;
}

// ---------------------------------------------------------------------------
// Main kernel: 8-lane cooperative groups.
// lane = (q = lane&3 c-quarter, hd = (lane>>2)&1 d-half, g = lane>>3 group).
// Thread owns 2 rows (rowb = w*8 + g*2 + {0,1}), accumulates partial y
// (its d-half) for c in [4q, 4q+4) as 2 f32x2 regs per row.
// W layout [l][dd][hd][16c]: group's 8 lanes read 8 distinct 16B chunks
// spanning all 32 banks -> conflict-free broadcast LDS.128.
// Embedding folded analytically: y += ev * H[t,c,l], H = emb @ W (in smem),
// added by hd==0 lanes only. Conversion is just x = nv * nfeat_half.
// One butterfly round (xor 4) merges d-halves; RED4 scatters output.
// ---------------------------------------------------------------------------
__global__ __launch_bounds__(NTHREADS, 4) void lrp_main_kernel(
    const float* __restrict__ nfeat,
    const void*  __restrict__ efeat_idx,
    const void*  __restrict__ n_row_probe,
    const void*  __restrict__ n_col, const float* __restrict__ n_val,
    const void*  __restrict__ e_col, const float* __restrict__ e_val,
    const void*  __restrict__ p_row, const float* __restrict__ p_val,
    const float* __restrict__ weights, const float* __restrict__ bias,
    const float* __restrict__ bond_emb,
    float* __restrict__ out)
{
    extern __shared__ float smem[];
    float*  sW   = smem;                    // 4096 : [l][dd][hd][c]
    float*  sH   = sW + 4096;               // 1024 : [l][t][c] = emb @ W
    float4* sRec = (float4*)(sH + 1024);    // 1024 recs {nc, t, nv, ev}
    float*  sBias= (float*)(sRec + 1024);   // 16

    const int tid   = threadIdx.x;
    const int pbase = blockIdx.x * PPB;
    const bool i64  = (((const int*)n_row_probe)[1] == 0);

    // ---- stage W in [l][dd][hd][c] layout
    #pragma unroll
    for (int i = tid; i < 4096; i += NTHREADS) {
        int c = i & 15, hdv = (i >> 4) & 1, dd = (i >> 5) & 7, l = i >> 8;
        int d = 8 * hdv + dd;
        sW[i] = weights[d * 256 + c * 16 + l];
    }
    // ---- precompute H[l][t][c] = sum_d emb[t,d] * W[d,c,l]
    #pragma unroll
    for (int i = tid; i < 1024; i += NTHREADS) {
        int c = i & 15, t = (i >> 4) & 3, l = i >> 6;
        float s = 0.f;
        #pragma unroll
        for (int d = 0; d < 16; ++d)
            s = fmaf(bond_emb[t * 16 + d], weights[d * 256 + c * 16 + l], s);
        sH[i] = s;
    }
    if (tid < 16) sBias[tid] = bias[tid];

    // ---- stage 1024 m-row records (pairs, coalesced; swizzled STS.128)
    const long long mhalf = (long long)pbase * 8;
    #pragma unroll 1
    for (int it = 0; it < 2; ++it) {
        int i  = it * NTHREADS + tid;   // pair idx 0..511
        int pl = i >> 3;                // p-local row 0..63
        int l  = (i << 1) & 15;         // even l
        int phys = pl ^ (i & 7);        // = pl ^ (l>>1), same for l and l+1
        if (pbase + pl < PP) {
            long long nc0, nc1, ec0, ec1;
            if (i64) {
                longlong2 ncp = ((const longlong2*)n_col)[mhalf + i];
                longlong2 ecp = ((const longlong2*)e_col)[mhalf + i];
                nc0 = ncp.x; nc1 = ncp.y; ec0 = ecp.x; ec1 = ecp.y;
            } else {
                int2 ncp = ((const int2*)n_col)[mhalf + i];
                int2 ecp = ((const int2*)e_col)[mhalf + i];
                nc0 = ncp.x; nc1 = ncp.y; ec0 = ecp.x; ec1 = ecp.y;
            }
            int t0 = i64 ? (int)((const long long*)efeat_idx)[ec0]
                         : ((const int*)efeat_idx)[(int)ec0];
            int t1 = i64 ? (int)((const long long*)efeat_idx)[ec1]
                         : ((const int*)efeat_idx)[(int)ec1];
            float2 nvp = ((const float2*)n_val)[mhalf + i];
            float2 evp = ((const float2*)e_val)[mhalf + i];
            sRec[l * 64 + phys] = make_float4(
                __int_as_float((int)nc0), __int_as_float(t0), nvp.x, evp.x);
            sRec[(l + 1) * 64 + phys] = make_float4(
                __int_as_float((int)nc1), __int_as_float(t1), nvp.y, evp.y);
        } else {
            float4 z = make_float4(0.f, 0.f, 0.f, 0.f);
            sRec[l * 64 + phys] = z;
            sRec[(l + 1) * 64 + phys] = z;
        }
    }
    __syncthreads();    // the only block-wide barrier

    const int lane = tid & 31;
    const int w    = tid >> 5;
    const int q    = lane & 3;
    const int hd   = (lane >> 2) & 1;
    const int rowb = w * 8 + (lane >> 3) * 2;   // rows rowb, rowb+1

    const float4* nf4 = (const float4*)nfeat;
    const ulonglong2* sW2 = (const ulonglong2*)sW;
    const ulonglong2* sH2 = (const ulonglong2*)sH;

    unsigned long long acc[2][2];
    acc[0][0] = 0ull; acc[0][1] = 0ull; acc[1][0] = 0ull; acc[1][1] = 0ull;

    float4 ga[2], gb[2];     // nfeat row halves for this thread's d-half
    float  nv[2], ev[2];
    int    tt[2];

    // prologue: records + gathers for l = 0
    #pragma unroll
    for (int r = 0; r < 2; ++r) {
        float4 rec = sRec[rowb + r];            // l=0 swizzle = 0
        nv[r] = rec.z; ev[r] = rec.w; tt[r] = __float_as_int(rec.y);
        const float4* base = nf4 + __float_as_int(rec.x) * 4 + 2 * hd;
        ga[r] = __ldcs(base); gb[r] = __ldcs(base + 1);
    }

    #pragma unroll 1
    for (int l = 0; l < 16; ++l) {
        // ---- convert: x = nv * nfeat_half (8 floats per row)
        float xf[2][8];
        #pragma unroll
        for (int r = 0; r < 2; ++r) {
            xf[r][0] = nv[r] * ga[r].x;  xf[r][1] = nv[r] * ga[r].y;
            xf[r][2] = nv[r] * ga[r].z;  xf[r][3] = nv[r] * ga[r].w;
            xf[r][4] = nv[r] * gb[r].x;  xf[r][5] = nv[r] * gb[r].y;
            xf[r][6] = nv[r] * gb[r].z;  xf[r][7] = nv[r] * gb[r].w;
        }
        // ---- embedding term (once per row: hd==0 lanes only)
        if (hd == 0) {
            #pragma unroll
            for (int r = 0; r < 2; ++r) {
                unsigned long long e2; PACK2(e2, __float_as_uint(ev[r]));
                ulonglong2 hw = sH2[(l * 4 + tt[r]) * 4 + q];
                FMAX2(acc[r][0], e2, hw.x);
                FMAX2(acc[r][1], e2, hw.y);
            }
        }
        // ---- prefetch next l's records + gathers (hidden under FMA below)
        if (l < 15) {
            int swz = ((l + 1) >> 1) & 7;
            #pragma unroll
            for (int r = 0; r < 2; ++r) {
                float4 rec = sRec[(l + 1) * 64 + ((rowb + r) ^ swz)];
                nv[r] = rec.z; ev[r] = rec.w; tt[r] = __float_as_int(rec.y);
                const float4* base = nf4 + __float_as_int(rec.x) * 4 + 2 * hd;
                ga[r] = __ldcs(base); gb[r] = __ldcs(base + 1);
            }
        }
        // ---- accumulate: conflict-free W broadcast, own d-half
        #pragma unroll
        for (int dd = 0; dd < 8; ++dd) {
            ulonglong2 w2 = sW2[((l * 8 + dd) * 2 + hd) * 4 + q];
            unsigned long long a0, a1;
            PACK2(a0, __float_as_uint(xf[0][dd]));
            PACK2(a1, __float_as_uint(xf[1][dd]));
            FMAX2(acc[0][0], a0, w2.x); FMAX2(acc[0][1], a0, w2.y);
            FMAX2(acc[1][0], a1, w2.x); FMAX2(acc[1][1], a1, w2.y);
        }
    }

    // ---- butterfly over d-halves (xor 4): both hd lanes get full y
    #pragma unroll
    for (int r = 0; r < 2; ++r)
        #pragma unroll
        for (int j = 0; j < 2; ++j) {
            unsigned long long o = __shfl_xor_sync(0xffffffffu, acc[r][j], 4, 32);
            ADD2(acc[r][j], o);
        }

    // ---- epilogue: lane (q, hd) writes c-quarter q of row rowb+hd
    {
        int r = hd;
        int p = pbase + rowb + r;
        if (p < PP) {
            long long pr = i64 ? ((const long long*)p_row)[p]
                               : (long long)((const int*)p_row)[p];
            float pv = p_val[p];
            float4 fd = __ldcs((const float4*)(g_fd + pr * 16 + 4 * q));
            unsigned int lo, hi;
            float y0, y1, y2, y3;
            asm("mov.b64 {%0, %1}, %2;" : "=r"(lo), "=r"(hi) : "l"(acc[r][0]));
            y0 = __uint_as_float(lo); y1 = __uint_as_float(hi);
            asm("mov.b64 {%0, %1}, %2;" : "=r"(lo), "=r"(hi) : "l"(acc[r][1]));
            y2 = __uint_as_float(lo); y3 = __uint_as_float(hi);
            float v0 = fmaxf(y0 + sBias[4 * q + 0], 0.f) * pv * fd.x;
            float v1 = fmaxf(y1 + sBias[4 * q + 1], 0.f) * pv * fd.y;
            float v2 = fmaxf(y2 + sBias[4 * q + 2], 0.f) * pv * fd.z;
            float v3 = fmaxf(y3 + sBias[4 * q + 3], 0.f) * pv * fd.w;
            const float* dst = out + pr * 16 + 4 * q;
            RED4(dst, v0, v1, v2, v3);
        }
    }
}

extern "C" void kernel_launch(void* const* d_in, const int* in_sizes, int n_in,
                              void* d_out, int out_size)
{
    const float* nfeat     = (const float*)d_in[0];
    const void*  efeat_idx = d_in[1];
    const void*  n_row     = d_in[2];
    const void*  n_col     = d_in[3];
    const float* n_val     = (const float*)d_in[4];
    const void*  e_col     = d_in[6];
    const float* e_val     = (const float*)d_in[7];
    const void*  p_row     = d_in[8];
    const float* p_val     = (const float*)d_in[10];
    const float* degs      = (const float*)d_in[11];
    const float* weights   = (const float*)d_in[12];
    const float* bias      = (const float*)d_in[13];
    const float* W0        = (const float*)d_in[14];
    const float* b0        = (const float*)d_in[15];
    const float* W1        = (const float*)d_in[16];
    const float* b1        = (const float*)d_in[17];
    const float* bond_emb  = (const float*)d_in[18];
    float* out = (float*)d_out;

    // fd (+ output zeroing) first; main kernel LAST so ncu -s 5 -c 1 captures it
    fd_pre_kernel<<<(NN + 255) / 256, 256>>>(degs, W0, b0, W1, b1, out);

    const int smem_bytes = (4096 + 1024) * 4 + 1024 * 16 + 64;  // 36,928 B
    cudaFuncSetAttribute(lrp_main_kernel,
                         cudaFuncAttributeMaxDynamicSharedMemorySize, smem_bytes);
    int grid = (PP + PPB - 1) / PPB;  // 3907
    lrp_main_kernel<<<grid, NTHREADS, smem_bytes>>>(
        nfeat, efeat_idx, n_row, n_col, n_val, e_col, e_val,
        p_row, p_val, weights, bias, bond_emb, out);
}

// round 12
// speedup vs baseline: 1.9051x; 1.9051x over previous
#include <cuda_runtime.h>
#include <cstdint>

#define NN 100000
#define PP 250000
#define PPB 128
#define NTHREADS 256

__device__ float g_fd[NN * 16];

// ---- packed f32x2 (fd_pre only) ----
#define FMAX2(acc, a, b) \
    asm("fma.rn.f32x2 %0, %1, %2, %0;" : "+l"(acc) : "l"(a), "l"(b))
#define PACK2(dst, src) \
    asm("mov.b64 %0, {%1, %1};" : "=l"(dst) : "r"(src))
#define RED2(ptr, a, b) \
    asm volatile("red.global.add.v2.f32 [%0], {%1,%2};" \
                 :: "l"(ptr), "f"(a), "f"(b) : "memory")

// ---------------------------------------------------------------------------
// Kernel 1: fd into g_fd; zero d_out.
// ---------------------------------------------------------------------------
__global__ __launch_bounds__(256) void fd_pre_kernel(
    const float* __restrict__ degs,
    const float* __restrict__ W0, const float* __restrict__ b0,
    const float* __restrict__ W1, const float* __restrict__ b1,
    float* __restrict__ out)
{
    __shared__ float sw0[32], sb0[32];
    __shared__ ulonglong2 sw1v[128];
    __shared__ unsigned long long sb1p[8];

    int tid = threadIdx.x;
    if (tid < 32) { sw0[tid] = W0[tid]; sb0[tid] = b0[tid]; }
    if (tid < 128) sw1v[tid] = ((const ulonglong2*)W1)[tid];
    if (tid < 8)  sb1p[tid] = ((const unsigned long long*)b1)[tid];
    __syncthreads();

    int n = blockIdx.x * 256 + tid;
    if (n >= NN) return;

    unsigned long long acc[8];
    #pragma unroll
    for (int i = 0; i < 8; ++i) acc[i] = sb1p[i];

    float dg = degs[n];
    #pragma unroll
    for (int j = 0; j < 32; ++j) {
        float h = fmaxf(fmaf(dg, sw0[j], sb0[j]), 0.f);
        unsigned long long hh; PACK2(hh, __float_as_uint(h));
        const ulonglong2* wp = sw1v + j * 4;
        ulonglong2 wA = wp[0], wB = wp[1], wC = wp[2], wD = wp[3];
        FMAX2(acc[0], hh, wA.x); FMAX2(acc[1], hh, wA.y);
        FMAX2(acc[2], hh, wB.x); FMAX2(acc[3], hh, wB.y);
        FMAX2(acc[4], hh, wC.x); FMAX2(acc[5], hh, wC.y);
        FMAX2(acc[6], hh, wD.x); FMAX2(acc[7], hh, wD.y);
    }

    ulonglong2* fdv = (ulonglong2*)(g_fd + n * 16);
    fdv[0] = make_ulonglong2(acc[0], acc[1]);
    fdv[1] = make_ulonglong2(acc[2], acc[3]);
    fdv[2] = make_ulonglong2(acc[4], acc[5]);
    fdv[3] = make_ulonglong2(acc[6], acc[7]);

    float4 z = make_float4(0.f, 0.f, 0.f, 0.f);
    float4* ov = (float4*)(out + n * 16);
    ov[0] = z; ov[1] = z; ov[2] = z; ov[3] = z;
}

// ---------------------------------------------------------------------------
// Main kernel: warp-level mma.sync bf16 split-single GEMM.
// Per warp: 16 p-rows (M=16), N=16 (two n8 tiles), K=256 (16 chunks = l).
// A frags built in registers straight from the gather; B = W^T from smem
// via ldmatrix; y = Ah*Bh + Ah*Bl + Al*Bh (f32 accum).
// ---------------------------------------------------------------------------
#define OFF_BH   0
#define OFF_BL   8192
#define OFF_REC  16384
#define OFF_EMB  (16384 + 32768)
#define OFF_BIAS (OFF_EMB + 256)
#define SMEM_TOTAL (OFF_BIAS + 64)     // 49,472 B

__device__ __forceinline__ uint32_t smem_u32(const void* p) {
    uint32_t a;
    asm("{ .reg .u64 t; cvta.to.shared.u64 t, %1; cvt.u32.u64 %0, t; }"
        : "=r"(a) : "l"(p));
    return a;
}

#define LDMX2(r0, r1, addr) \
    asm volatile("ldmatrix.sync.aligned.m8n8.x2.shared.b16 {%0,%1}, [%2];" \
                 : "=r"(r0), "=r"(r1) : "r"(addr))

#define MMA(C, A0, A1, A2, A3, B0, B1) \
    asm volatile("mma.sync.aligned.m16n8k16.row.col.f32.bf16.bf16.f32 " \
                 "{%0,%1,%2,%3}, {%4,%5,%6,%7}, {%8,%9}, {%0,%1,%2,%3};" \
                 : "+f"(C[0]), "+f"(C[1]), "+f"(C[2]), "+f"(C[3]) \
                 : "r"(A0), "r"(A1), "r"(A2), "r"(A3), "r"(B0), "r"(B1))

__global__ __launch_bounds__(NTHREADS, 3) void lrp_main_kernel(
    const float* __restrict__ nfeat,
    const void*  __restrict__ efeat_idx,
    const void*  __restrict__ n_row_probe,
    const void*  __restrict__ n_col, const float* __restrict__ n_val,
    const void*  __restrict__ e_col, const float* __restrict__ e_val,
    const void*  __restrict__ p_row, const float* __restrict__ p_val,
    const float* __restrict__ weights, const float* __restrict__ bias,
    const float* __restrict__ bond_emb,
    float* __restrict__ out)
{
    extern __shared__ __align__(128) char smem[];
    const uint32_t sbase = smem_u32(smem);

    const int tid   = threadIdx.x;
    const int wid   = tid >> 5;
    const int lane  = tid & 31;
    const int pbase = blockIdx.x * PPB;
    const bool i64  = (((const int*)n_row_probe)[1] == 0);

    // ---- stage B = W^T split to bf16 hi/lo: [l][khalf][c][8 bf16]
    #pragma unroll 1
    for (int i = tid; i < 4096; i += NTHREADS) {
        int d = i >> 8, c = (i >> 4) & 15, l = i & 15;   // i = d*256+c*16+l
        float v = weights[i];
        uint32_t ph;
        asm("cvt.rn.bf16x2.f32 %0, %1, %1;" : "=r"(ph) : "f"(v));
        float vl = v - __uint_as_float(ph << 16);
        uint32_t pl2;
        asm("cvt.rn.bf16x2.f32 %0, %1, %1;" : "=r"(pl2) : "f"(vl));
        int off = l * 512 + (d >> 3) * 256 + c * 16 + (d & 7) * 2;
        *(uint16_t*)(smem + OFF_BH + off) = (uint16_t)(ph & 0xFFFF);
        *(uint16_t*)(smem + OFF_BL + off) = (uint16_t)(pl2 & 0xFFFF);
    }
    if (tid < 64) ((float*)(smem + OFF_EMB))[tid]  = bond_emb[tid];
    if (tid < 16) ((float*)(smem + OFF_BIAS))[tid] = bias[tid];

    // ---- stage 2048 m-row records {nc, t, nv, ev}, column-swizzled
    const long long mhalf = (long long)pbase * 8;
    #pragma unroll 1
    for (int it = 0; it < 4; ++it) {
        int i  = it * NTHREADS + tid;   // pair idx 0..1023
        int pl = i >> 3;                // p-local 0..127
        int l2 = (i << 1) & 15;         // even l
        float4 rec0, rec1;
        if (pbase + pl < PP) {
            long long nc0, nc1, ec0, ec1;
            if (i64) {
                longlong2 ncp = ((const longlong2*)n_col)[mhalf + i];
                longlong2 ecp = ((const longlong2*)e_col)[mhalf + i];
                nc0 = ncp.x; nc1 = ncp.y; ec0 = ecp.x; ec1 = ecp.y;
            } else {
                int2 ncp = ((const int2*)n_col)[mhalf + i];
                int2 ecp = ((const int2*)e_col)[mhalf + i];
                nc0 = ncp.x; nc1 = ncp.y; ec0 = ecp.x; ec1 = ecp.y;
            }
            int t0 = i64 ? (int)((const long long*)efeat_idx)[ec0]
                         : ((const int*)efeat_idx)[(int)ec0];
            int t1 = i64 ? (int)((const long long*)efeat_idx)[ec1]
                         : ((const int*)efeat_idx)[(int)ec1];
            float2 nvp = ((const float2*)n_val)[mhalf + i];
            float2 evp = ((const float2*)e_val)[mhalf + i];
            rec0 = make_float4(__int_as_float((int)nc0), __int_as_float(t0), nvp.x, evp.x);
            rec1 = make_float4(__int_as_float((int)nc1), __int_as_float(t1), nvp.y, evp.y);
        } else {
            rec0 = make_float4(0.f, 0.f, 0.f, 0.f);
            rec1 = rec0;
        }
        int ph0 = (pl & ~7) | ((pl + l2) & 7);
        int ph1 = (pl & ~7) | ((pl + l2 + 1) & 7);
        *(float4*)(smem + OFF_REC + l2 * 2048 + ph0 * 16)       = rec0;
        *(float4*)(smem + OFF_REC + (l2 + 1) * 2048 + ph1 * 16) = rec1;
    }
    __syncthreads();

    // ---- per-warp mma mainloop: warp owns rows [16*wid, 16*wid+16)
    const int g = lane >> 2;        // 0..7
    const int j = lane & 3;         // k-piece
    const int row0 = 16 * wid + g;  // local rows row0, row0+8
    const float2* nf2 = (const float2*)nfeat;
    const float2* eb2 = (const float2*)(smem + OFF_EMB);

    float D0[4] = {0.f, 0.f, 0.f, 0.f};
    float D1[4] = {0.f, 0.f, 0.f, 0.f};

    float2 cu[2], cv[2]; float cnv[2], cev[2]; int ct[2];
    // prologue: recs + gathers for l = 0
    #pragma unroll
    for (int r = 0; r < 2; ++r) {
        int row = row0 + 8 * r;
        int phys = (row & ~7) | (row & 7);  // l=0
        float4 rec = *(const float4*)(smem + OFF_REC + phys * 16);
        int nc = __float_as_int(rec.x);
        ct[r] = __float_as_int(rec.y); cnv[r] = rec.z; cev[r] = rec.w;
        const float2* base = nf2 + (long long)nc * 8;
        cu[r] = __ldg(base + j);
        cv[r] = __ldg(base + 4 + j);
    }

    const uint32_t baddr_h = sbase + OFF_BH + ((lane >> 3) & 1) * 256 + (lane & 7) * 16;
    const uint32_t baddr_l = sbase + OFF_BL + ((lane >> 3) & 1) * 256 + (lane & 7) * 16;

    #pragma unroll 1
    for (int l = 0; l < 16; ++l) {
        // ---- build A frags (hi/lo) from current gather
        uint32_t ah[4], al[4];
        #pragma unroll
        for (int r = 0; r < 2; ++r) {
            float2 e0 = eb2[ct[r] * 8 + j];
            float2 e1 = eb2[ct[r] * 8 + 4 + j];
            float x0 = fmaf(cnv[r], cu[r].x, cev[r] * e0.x);
            float x1 = fmaf(cnv[r], cu[r].y, cev[r] * e0.y);
            float x2 = fmaf(cnv[r], cv[r].x, cev[r] * e1.x);
            float x3 = fmaf(cnv[r], cv[r].y, cev[r] * e1.y);
            uint32_t h01, h23;
            asm("cvt.rn.bf16x2.f32 %0, %1, %2;" : "=r"(h01) : "f"(x1), "f"(x0));
            asm("cvt.rn.bf16x2.f32 %0, %1, %2;" : "=r"(h23) : "f"(x3), "f"(x2));
            float y0 = x0 - __uint_as_float(h01 << 16);
            float y1 = x1 - __uint_as_float(h01 & 0xFFFF0000u);
            float y2 = x2 - __uint_as_float(h23 << 16);
            float y3 = x3 - __uint_as_float(h23 & 0xFFFF0000u);
            uint32_t q01, q23;
            asm("cvt.rn.bf16x2.f32 %0, %1, %2;" : "=r"(q01) : "f"(y1), "f"(y0));
            asm("cvt.rn.bf16x2.f32 %0, %1, %2;" : "=r"(q23) : "f"(y3), "f"(y2));
            ah[r] = h01; ah[2 + r] = h23;
            al[r] = q01; al[2 + r] = q23;
        }
        // ---- prefetch next l's recs + gathers
        if (l < 15) {
            #pragma unroll
            for (int r = 0; r < 2; ++r) {
                int row = row0 + 8 * r;
                int phys = (row & ~7) | ((row + l + 1) & 7);
                float4 rec = *(const float4*)(smem + OFF_REC + (l + 1) * 2048 + phys * 16);
                int nc = __float_as_int(rec.x);
                ct[r] = __float_as_int(rec.y); cnv[r] = rec.z; cev[r] = rec.w;
                const float2* base = nf2 + (long long)nc * 8;
                cu[r] = __ldg(base + j);
                cv[r] = __ldg(base + 4 + j);
            }
        }
        // ---- B frags for this l (W^T hi/lo, two n8 tiles)
        uint32_t bh0a, bh0b, bh1a, bh1b, bl0a, bl0b, bl1a, bl1b;
        LDMX2(bh0a, bh0b, baddr_h + l * 512);
        LDMX2(bh1a, bh1b, baddr_h + l * 512 + 128);
        LDMX2(bl0a, bl0b, baddr_l + l * 512);
        LDMX2(bl1a, bl1b, baddr_l + l * 512 + 128);
        // ---- 6 mma: Ah*Bh + Ah*Bl + Al*Bh, both n-tiles
        MMA(D0, ah[0], ah[1], ah[2], ah[3], bh0a, bh0b);
        MMA(D0, ah[0], ah[1], ah[2], ah[3], bl0a, bl0b);
        MMA(D0, al[0], al[1], al[2], al[3], bh0a, bh0b);
        MMA(D1, ah[0], ah[1], ah[2], ah[3], bh1a, bh1b);
        MMA(D1, ah[0], ah[1], ah[2], ah[3], bl1a, bl1b);
        MMA(D1, al[0], al[1], al[2], al[3], bh1a, bh1b);
    }

    // ---- epilogue: lane holds rows row0, row0+8; cols 2j,2j+1 (+8 for D1)
    const float* sBias = (const float*)(smem + OFF_BIAS);
    const int c0 = 2 * j;
    #pragma unroll
    for (int r = 0; r < 2; ++r) {
        int p = pbase + row0 + 8 * r;
        if (p >= PP) continue;
        long long pr = i64 ? ((const long long*)p_row)[p]
                           : (long long)((const int*)p_row)[p];
        float pv = p_val[p];
        float2 fdA = *(const float2*)(g_fd + pr * 16 + c0);
        float2 fdB = *(const float2*)(g_fd + pr * 16 + 8 + c0);
        float vA0 = fmaxf(D0[2 * r + 0] + sBias[c0],     0.f) * pv * fdA.x;
        float vA1 = fmaxf(D0[2 * r + 1] + sBias[c0 + 1], 0.f) * pv * fdA.y;
        float vB0 = fmaxf(D1[2 * r + 0] + sBias[8 + c0],     0.f) * pv * fdB.x;
        float vB1 = fmaxf(D1[2 * r + 1] + sBias[8 + c0 + 1], 0.f) * pv * fdB.y;
        RED2(out + pr * 16 + c0, vA0, vA1);
        RED2(out + pr * 16 + 8 + c0, vB0, vB1);
    }
}

extern "C" void kernel_launch(void* const* d_in, const int* in_sizes, int n_in,
                              void* d_out, int out_size)
{
    const float* nfeat     = (const float*)d_in[0];
    const void*  efeat_idx = d_in[1];
    const void*  n_row     = d_in[2];
    const void*  n_col     = d_in[3];
    const float* n_val     = (const float*)d_in[4];
    const void*  e_col     = d_in[6];
    const float* e_val     = (const float*)d_in[7];
    const void*  p_row     = d_in[8];
    const float* p_val     = (const float*)d_in[10];
    const float* degs      = (const float*)d_in[11];
    const float* weights   = (const float*)d_in[12];
    const float* bias      = (const float*)d_in[13];
    const float* W0        = (const float*)d_in[14];
    const float* b0        = (const float*)d_in[15];
    const float* W1        = (const float*)d_in[16];
    const float* b1        = (const float*)d_in[17];
    const float* bond_emb  = (const float*)d_in[18];
    float* out = (float*)d_out;

    fd_pre_kernel<<<(NN + 255) / 256, 256>>>(degs, W0, b0, W1, b1, out);

    cudaFuncSetAttribute(lrp_main_kernel,
                         cudaFuncAttributeMaxDynamicSharedMemorySize, SMEM_TOTAL);
    int grid = (PP + PPB - 1) / PPB;  // 1954
    lrp_main_kernel<<<grid, NTHREADS, SMEM_TOTAL>>>(
        nfeat, efeat_idx, n_row, n_col, n_val, e_col, e_val,
        p_row, p_val, weights, bias, bond_emb, out);
}

// round 13
// speedup vs baseline: 2.0300x; 1.0656x over previous
#include <cuda_runtime.h>
#include <cstdint>

#define NN 100000
#define PP 250000
#define PPB 128
#define NTHREADS 256

__device__ float g_fd[NN * 16];

// ---- packed f32x2 (fd_pre only) ----
#define FMAX2(acc, a, b) \
    asm("fma.rn.f32x2 %0, %1, %2, %0;" : "+l"(acc) : "l"(a), "l"(b))
#define PACK2(dst, src) \
    asm("mov.b64 %0, {%1, %1};" : "=l"(dst) : "r"(src))
#define RED2(ptr, a, b) \
    asm volatile("red.global.add.v2.f32 [%0], {%1,%2};" \
                 :: "l"(ptr), "f"(a), "f"(b) : "memory")

// ---------------------------------------------------------------------------
// Kernel 1: fd into g_fd; zero d_out.
// ---------------------------------------------------------------------------
__global__ __launch_bounds__(256) void fd_pre_kernel(
    const float* __restrict__ degs,
    const float* __restrict__ W0, const float* __restrict__ b0,
    const float* __restrict__ W1, const float* __restrict__ b1,
    float* __restrict__ out)
{
    __shared__ float sw0[32], sb0[32];
    __shared__ ulonglong2 sw1v[128];
    __shared__ unsigned long long sb1p[8];

    int tid = threadIdx.x;
    if (tid < 32) { sw0[tid] = W0[tid]; sb0[tid] = b0[tid]; }
    if (tid < 128) sw1v[tid] = ((const ulonglong2*)W1)[tid];
    if (tid < 8)  sb1p[tid] = ((const unsigned long long*)b1)[tid];
    __syncthreads();

    int n = blockIdx.x * 256 + tid;
    if (n >= NN) return;

    unsigned long long acc[8];
    #pragma unroll
    for (int i = 0; i < 8; ++i) acc[i] = sb1p[i];

    float dg = degs[n];
    #pragma unroll
    for (int j = 0; j < 32; ++j) {
        float h = fmaxf(fmaf(dg, sw0[j], sb0[j]), 0.f);
        unsigned long long hh; PACK2(hh, __float_as_uint(h));
        const ulonglong2* wp = sw1v + j * 4;
        ulonglong2 wA = wp[0], wB = wp[1], wC = wp[2], wD = wp[3];
        FMAX2(acc[0], hh, wA.x); FMAX2(acc[1], hh, wA.y);
        FMAX2(acc[2], hh, wB.x); FMAX2(acc[3], hh, wB.y);
        FMAX2(acc[4], hh, wC.x); FMAX2(acc[5], hh, wC.y);
        FMAX2(acc[6], hh, wD.x); FMAX2(acc[7], hh, wD.y);
    }

    ulonglong2* fdv = (ulonglong2*)(g_fd + n * 16);
    fdv[0] = make_ulonglong2(acc[0], acc[1]);
    fdv[1] = make_ulonglong2(acc[2], acc[3]);
    fdv[2] = make_ulonglong2(acc[4], acc[5]);
    fdv[3] = make_ulonglong2(acc[6], acc[7]);

    float4 z = make_float4(0.f, 0.f, 0.f, 0.f);
    float4* ov = (float4*)(out + n * 16);
    ov[0] = z; ov[1] = z; ov[2] = z; ov[3] = z;
}

// ---------------------------------------------------------------------------
// Main kernel: warp-level mma.sync bf16 split-single GEMM with a K-axis
// permutation so A-fragment lane j sources d in {4j..4j+3} = ONE float4.
// pi(slot-pair ps) -> d-pair: {0..7} -> {0,2,4,6,1,3,5,7}; B staged at
// slot s = pi^-1(d); MMA/ldmatrix unchanged; result identical.
// ---------------------------------------------------------------------------
#define OFF_BH   0
#define OFF_BL   8192
#define OFF_REC  16384
#define OFF_EMB  (16384 + 32768)
#define OFF_BIAS (OFF_EMB + 256)
#define SMEM_TOTAL (OFF_BIAS + 64)     // 49,472 B

__device__ __forceinline__ uint32_t smem_u32(const void* p) {
    uint32_t a;
    asm("{ .reg .u64 t; cvta.to.shared.u64 t, %1; cvt.u32.u64 %0, t; }"
        : "=r"(a) : "l"(p));
    return a;
}

#define LDMX2(r0, r1, addr) \
    asm volatile("ldmatrix.sync.aligned.m8n8.x2.shared.b16 {%0,%1}, [%2];" \
                 : "=r"(r0), "=r"(r1) : "r"(addr))

#define MMA(C, A0, A1, A2, A3, B0, B1) \
    asm volatile("mma.sync.aligned.m16n8k16.row.col.f32.bf16.bf16.f32 " \
                 "{%0,%1,%2,%3}, {%4,%5,%6,%7}, {%8,%9}, {%0,%1,%2,%3};" \
                 : "+f"(C[0]), "+f"(C[1]), "+f"(C[2]), "+f"(C[3]) \
                 : "r"(A0), "r"(A1), "r"(A2), "r"(A3), "r"(B0), "r"(B1))

__global__ __launch_bounds__(NTHREADS, 4) void lrp_main_kernel(
    const float* __restrict__ nfeat,
    const void*  __restrict__ efeat_idx,
    const void*  __restrict__ n_row_probe,
    const void*  __restrict__ n_col, const float* __restrict__ n_val,
    const void*  __restrict__ e_col, const float* __restrict__ e_val,
    const void*  __restrict__ p_row, const float* __restrict__ p_val,
    const float* __restrict__ weights, const float* __restrict__ bias,
    const float* __restrict__ bond_emb,
    float* __restrict__ out)
{
    extern __shared__ __align__(128) char smem[];
    const uint32_t sbase = smem_u32(smem);

    const int tid   = threadIdx.x;
    const int wid   = tid >> 5;
    const int lane  = tid & 31;
    const int pbase = blockIdx.x * PPB;
    const bool i64  = (((const int*)n_row_probe)[1] == 0);

    // ---- stage B = W^T split to bf16 hi/lo at permuted K slot:
    //      d-pair pd -> slot-pair ps = (pd odd) ? 4 + pd/2 : pd/2
    #pragma unroll 1
    for (int i = tid; i < 4096; i += NTHREADS) {
        int d = i >> 8, c = (i >> 4) & 15, l = i & 15;   // i = d*256+c*16+l
        float v = weights[i];
        uint32_t ph;
        asm("cvt.rn.bf16x2.f32 %0, %1, %1;" : "=r"(ph) : "f"(v));
        float vl = v - __uint_as_float(ph << 16);
        uint32_t pl2;
        asm("cvt.rn.bf16x2.f32 %0, %1, %1;" : "=r"(pl2) : "f"(vl));
        int pd = d >> 1;
        int ps = (pd & 1) ? 4 + (pd >> 1) : (pd >> 1);
        int s  = 2 * ps + (d & 1);
        int off = l * 512 + (s >> 3) * 256 + c * 16 + (s & 7) * 2;
        *(uint16_t*)(smem + OFF_BH + off) = (uint16_t)(ph & 0xFFFF);
        *(uint16_t*)(smem + OFF_BL + off) = (uint16_t)(pl2 & 0xFFFF);
    }
    if (tid < 64) ((float*)(smem + OFF_EMB))[tid]  = bond_emb[tid];
    if (tid < 16) ((float*)(smem + OFF_BIAS))[tid] = bias[tid];

    // ---- stage 2048 m-row records {nc, t, nv, ev}, column-swizzled
    const long long mhalf = (long long)pbase * 8;
    #pragma unroll 1
    for (int it = 0; it < 4; ++it) {
        int i  = it * NTHREADS + tid;   // pair idx 0..1023
        int pl = i >> 3;                // p-local 0..127
        int l2 = (i << 1) & 15;         // even l
        float4 rec0, rec1;
        if (pbase + pl < PP) {
            long long nc0, nc1, ec0, ec1;
            if (i64) {
                longlong2 ncp = ((const longlong2*)n_col)[mhalf + i];
                longlong2 ecp = ((const longlong2*)e_col)[mhalf + i];
                nc0 = ncp.x; nc1 = ncp.y; ec0 = ecp.x; ec1 = ecp.y;
            } else {
                int2 ncp = ((const int2*)n_col)[mhalf + i];
                int2 ecp = ((const int2*)e_col)[mhalf + i];
                nc0 = ncp.x; nc1 = ncp.y; ec0 = ecp.x; ec1 = ecp.y;
            }
            int t0 = i64 ? (int)((const long long*)efeat_idx)[ec0]
                         : ((const int*)efeat_idx)[(int)ec0];
            int t1 = i64 ? (int)((const long long*)efeat_idx)[ec1]
                         : ((const int*)efeat_idx)[(int)ec1];
            float2 nvp = ((const float2*)n_val)[mhalf + i];
            float2 evp = ((const float2*)e_val)[mhalf + i];
            rec0 = make_float4(__int_as_float((int)nc0), __int_as_float(t0), nvp.x, evp.x);
            rec1 = make_float4(__int_as_float((int)nc1), __int_as_float(t1), nvp.y, evp.y);
        } else {
            rec0 = make_float4(0.f, 0.f, 0.f, 0.f);
            rec1 = rec0;
        }
        int ph0 = (pl & ~7) | ((pl + l2) & 7);
        int ph1 = (pl & ~7) | ((pl + l2 + 1) & 7);
        *(float4*)(smem + OFF_REC + l2 * 2048 + ph0 * 16)       = rec0;
        *(float4*)(smem + OFF_REC + (l2 + 1) * 2048 + ph1 * 16) = rec1;
    }
    __syncthreads();

    // ---- per-warp mma mainloop: warp owns rows [16*wid, 16*wid+16)
    const int g = lane >> 2;        // 0..7
    const int j = lane & 3;         // k-piece: d in {4j..4j+3}
    const int row0 = 16 * wid + g;  // local rows row0, row0+8
    const float4* nf4 = (const float4*)nfeat;
    const float4* eb4 = (const float4*)(smem + OFF_EMB);

    float D0[4] = {0.f, 0.f, 0.f, 0.f};
    float D1[4] = {0.f, 0.f, 0.f, 0.f};

    float4 cx[2]; float cnv[2], cev[2]; int ct[2];
    // prologue: recs + gathers for l = 0
    #pragma unroll
    for (int r = 0; r < 2; ++r) {
        int row = row0 + 8 * r;
        int phys = (row & ~7) | (row & 7);  // l=0
        float4 rec = *(const float4*)(smem + OFF_REC + phys * 16);
        int nc = __float_as_int(rec.x);
        ct[r] = __float_as_int(rec.y); cnv[r] = rec.z; cev[r] = rec.w;
        cx[r] = __ldg(nf4 + (long long)nc * 4 + j);
    }

    const uint32_t baddr_h = sbase + OFF_BH + ((lane >> 3) & 1) * 256 + (lane & 7) * 16;
    const uint32_t baddr_l = sbase + OFF_BL + ((lane >> 3) & 1) * 256 + (lane & 7) * 16;

    #pragma unroll 1
    for (int l = 0; l < 16; ++l) {
        // ---- build A frags (hi/lo): d {4j..4j+3} contiguous
        uint32_t ah[4], al[4];
        #pragma unroll
        for (int r = 0; r < 2; ++r) {
            float4 e = eb4[ct[r] * 4 + j];
            float x0 = fmaf(cnv[r], cx[r].x, cev[r] * e.x);
            float x1 = fmaf(cnv[r], cx[r].y, cev[r] * e.y);
            float x2 = fmaf(cnv[r], cx[r].z, cev[r] * e.z);
            float x3 = fmaf(cnv[r], cx[r].w, cev[r] * e.w);
            uint32_t h01, h23;
            asm("cvt.rn.bf16x2.f32 %0, %1, %2;" : "=r"(h01) : "f"(x1), "f"(x0));
            asm("cvt.rn.bf16x2.f32 %0, %1, %2;" : "=r"(h23) : "f"(x3), "f"(x2));
            float y0 = x0 - __uint_as_float(h01 << 16);
            float y1 = x1 - __uint_as_float(h01 & 0xFFFF0000u);
            float y2 = x2 - __uint_as_float(h23 << 16);
            float y3 = x3 - __uint_as_float(h23 & 0xFFFF0000u);
            uint32_t q01, q23;
            asm("cvt.rn.bf16x2.f32 %0, %1, %2;" : "=r"(q01) : "f"(y1), "f"(y0));
            asm("cvt.rn.bf16x2.f32 %0, %1, %2;" : "=r"(q23) : "f"(y3), "f"(y2));
            ah[r] = h01; ah[2 + r] = h23;
            al[r] = q01; al[2 + r] = q23;
        }
        // ---- prefetch next l's recs + gathers
        if (l < 15) {
            #pragma unroll
            for (int r = 0; r < 2; ++r) {
                int row = row0 + 8 * r;
                int phys = (row & ~7) | ((row + l + 1) & 7);
                float4 rec = *(const float4*)(smem + OFF_REC + (l + 1) * 2048 + phys * 16);
                int nc = __float_as_int(rec.x);
                ct[r] = __float_as_int(rec.y); cnv[r] = rec.z; cev[r] = rec.w;
                cx[r] = __ldg(nf4 + (long long)nc * 4 + j);
            }
        }
        // ---- B frags for this l (W^T hi/lo, two n8 tiles)
        uint32_t bh0a, bh0b, bh1a, bh1b, bl0a, bl0b, bl1a, bl1b;
        LDMX2(bh0a, bh0b, baddr_h + l * 512);
        LDMX2(bh1a, bh1b, baddr_h + l * 512 + 128);
        LDMX2(bl0a, bl0b, baddr_l + l * 512);
        LDMX2(bl1a, bl1b, baddr_l + l * 512 + 128);
        // ---- 6 mma: Ah*Bh + Ah*Bl + Al*Bh, both n-tiles
        MMA(D0, ah[0], ah[1], ah[2], ah[3], bh0a, bh0b);
        MMA(D0, ah[0], ah[1], ah[2], ah[3], bl0a, bl0b);
        MMA(D0, al[0], al[1], al[2], al[3], bh0a, bh0b);
        MMA(D1, ah[0], ah[1], ah[2], ah[3], bh1a, bh1b);
        MMA(D1, ah[0], ah[1], ah[2], ah[3], bl1a, bl1b);
        MMA(D1, al[0], al[1], al[2], al[3], bh1a, bh1b);
    }

    // ---- epilogue: lane holds rows row0, row0+8; cols 2j,2j+1 (+8 for D1)
    const float* sBias = (const float*)(smem + OFF_BIAS);
    const int c0 = 2 * j;
    #pragma unroll
    for (int r = 0; r < 2; ++r) {
        int p = pbase + row0 + 8 * r;
        if (p >= PP) continue;
        long long pr = i64 ? ((const long long*)p_row)[p]
                           : (long long)((const int*)p_row)[p];
        float pv = p_val[p];
        float2 fdA = *(const float2*)(g_fd + pr * 16 + c0);
        float2 fdB = *(const float2*)(g_fd + pr * 16 + 8 + c0);
        float vA0 = fmaxf(D0[2 * r + 0] + sBias[c0],     0.f) * pv * fdA.x;
        float vA1 = fmaxf(D0[2 * r + 1] + sBias[c0 + 1], 0.f) * pv * fdA.y;
        float vB0 = fmaxf(D1[2 * r + 0] + sBias[8 + c0],     0.f) * pv * fdB.x;
        float vB1 = fmaxf(D1[2 * r + 1] + sBias[8 + c0 + 1], 0.f) * pv * fdB.y;
        RED2(out + pr * 16 + c0, vA0, vA1);
        RED2(out + pr * 16 + 8 + c0, vB0, vB1);
    }
}

extern "C" void kernel_launch(void* const* d_in, const int* in_sizes, int n_in,
                              void* d_out, int out_size)
{
    const float* nfeat     = (const float*)d_in[0];
    const void*  efeat_idx = d_in[1];
    const void*  n_row     = d_in[2];
    const void*  n_col     = d_in[3];
    const float* n_val     = (const float*)d_in[4];
    const void*  e_col     = d_in[6];
    const float* e_val     = (const float*)d_in[7];
    const void*  p_row     = d_in[8];
    const float* p_val     = (const float*)d_in[10];
    const float* degs      = (const float*)d_in[11];
    const float* weights   = (const float*)d_in[12];
    const float* bias      = (const float*)d_in[13];
    const float* W0        = (const float*)d_in[14];
    const float* b0        = (const float*)d_in[15];
    const float* W1        = (const float*)d_in[16];
    const float* b1        = (const float*)d_in[17];
    const float* bond_emb  = (const float*)d_in[18];
    float* out = (float*)d_out;

    fd_pre_kernel<<<(NN + 255) / 256, 256>>>(degs, W0, b0, W1, b1, out);

    cudaFuncSetAttribute(lrp_main_kernel,
                         cudaFuncAttributeMaxDynamicSharedMemorySize, SMEM_TOTAL);
    int grid = (PP + PPB - 1) / PPB;  // 1954
    lrp_main_kernel<<<grid, NTHREADS, SMEM_TOTAL>>>(
        nfeat, efeat_idx, n_row, n_col, n_val, e_col, e_val,
        p_row, p_val, weights, bias, bond_emb, out);
}

// round 14
// speedup vs baseline: 2.5333x; 1.2479x over previous
#include <cuda_runtime.h>
#include <cstdint>

#define NN 100000
#define PP 250000
#define PPB 128
#define NTHREADS 256

__device__ float g_fd[NN * 16];
__device__ __align__(16) unsigned char g_Bpack[16384];   // Bh[8KB] | Bl[8KB]

// ---- packed f32x2 (fd_pre only) ----
#define FMAX2(acc, a, b) \
    asm("fma.rn.f32x2 %0, %1, %2, %0;" : "+l"(acc) : "l"(a), "l"(b))
#define PACK2(dst, src) \
    asm("mov.b64 %0, {%1, %1};" : "=l"(dst) : "r"(src))
#define RED2(ptr, a, b) \
    asm volatile("red.global.add.v2.f32 [%0], {%1,%2};" \
                 :: "l"(ptr), "f"(a), "f"(b) : "memory")

// ---------------------------------------------------------------------------
// Kernel 1: fd into g_fd; zero d_out.
// ---------------------------------------------------------------------------
__global__ __launch_bounds__(256) void fd_pre_kernel(
    const float* __restrict__ degs,
    const float* __restrict__ W0, const float* __restrict__ b0,
    const float* __restrict__ W1, const float* __restrict__ b1,
    float* __restrict__ out)
{
    __shared__ float sw0[32], sb0[32];
    __shared__ ulonglong2 sw1v[128];
    __shared__ unsigned long long sb1p[8];

    int tid = threadIdx.x;
    if (tid < 32) { sw0[tid] = W0[tid]; sb0[tid] = b0[tid]; }
    if (tid < 128) sw1v[tid] = ((const ulonglong2*)W1)[tid];
    if (tid < 8)  sb1p[tid] = ((const unsigned long long*)b1)[tid];
    __syncthreads();

    int n = blockIdx.x * 256 + tid;
    if (n >= NN) return;

    unsigned long long acc[8];
    #pragma unroll
    for (int i = 0; i < 8; ++i) acc[i] = sb1p[i];

    float dg = degs[n];
    #pragma unroll
    for (int j = 0; j < 32; ++j) {
        float h = fmaxf(fmaf(dg, sw0[j], sb0[j]), 0.f);
        unsigned long long hh; PACK2(hh, __float_as_uint(h));
        const ulonglong2* wp = sw1v + j * 4;
        ulonglong2 wA = wp[0], wB = wp[1], wC = wp[2], wD = wp[3];
        FMAX2(acc[0], hh, wA.x); FMAX2(acc[1], hh, wA.y);
        FMAX2(acc[2], hh, wB.x); FMAX2(acc[3], hh, wB.y);
        FMAX2(acc[4], hh, wC.x); FMAX2(acc[5], hh, wC.y);
        FMAX2(acc[6], hh, wD.x); FMAX2(acc[7], hh, wD.y);
    }

    ulonglong2* fdv = (ulonglong2*)(g_fd + n * 16);
    fdv[0] = make_ulonglong2(acc[0], acc[1]);
    fdv[1] = make_ulonglong2(acc[2], acc[3]);
    fdv[2] = make_ulonglong2(acc[4], acc[5]);
    fdv[3] = make_ulonglong2(acc[6], acc[7]);

    float4 z = make_float4(0.f, 0.f, 0.f, 0.f);
    float4* ov = (float4*)(out + n * 16);
    ov[0] = z; ov[1] = z; ov[2] = z; ov[3] = z;
}

// ---------------------------------------------------------------------------
// Kernel 2: split weights to bf16 hi/lo, K-permuted, ldmatrix-ready layout.
// Runs once per call (~2us); every main CTA then does a linear 16KB copy.
// ---------------------------------------------------------------------------
__global__ __launch_bounds__(256) void b_pre_kernel(const float* __restrict__ weights)
{
    int i = blockIdx.x * 256 + threadIdx.x;   // 0..4095
    if (i >= 4096) return;
    int d = i >> 8, c = (i >> 4) & 15, l = i & 15;   // i = d*256 + c*16 + l
    float v = weights[i];
    uint32_t ph;
    asm("cvt.rn.bf16x2.f32 %0, %1, %1;" : "=r"(ph) : "f"(v));
    float vl = v - __uint_as_float(ph << 16);
    uint32_t pl2;
    asm("cvt.rn.bf16x2.f32 %0, %1, %1;" : "=r"(pl2) : "f"(vl));
    int pd = d >> 1;
    int ps = (pd & 1) ? 4 + (pd >> 1) : (pd >> 1);
    int s  = 2 * ps + (d & 1);
    int off = l * 512 + (s >> 3) * 256 + c * 16 + (s & 7) * 2;
    *(uint16_t*)(g_Bpack + off)        = (uint16_t)(ph & 0xFFFF);
    *(uint16_t*)(g_Bpack + 8192 + off) = (uint16_t)(pl2 & 0xFFFF);
}

// ---------------------------------------------------------------------------
// Main kernel: warp-level mma.sync bf16 split-single GEMM, K-permuted so
// A-fragment lane j sources d in {4j..4j+3} = one float4 gather.
// ---------------------------------------------------------------------------
#define OFF_BH   0
#define OFF_BL   8192
#define OFF_REC  16384
#define OFF_EMB  (16384 + 32768)
#define OFF_BIAS (OFF_EMB + 256)
#define SMEM_TOTAL (OFF_BIAS + 64)     // 49,472 B

__device__ __forceinline__ uint32_t smem_u32(const void* p) {
    uint32_t a;
    asm("{ .reg .u64 t; cvta.to.shared.u64 t, %1; cvt.u32.u64 %0, t; }"
        : "=r"(a) : "l"(p));
    return a;
}

#define LDMX2(r0, r1, addr) \
    asm volatile("ldmatrix.sync.aligned.m8n8.x2.shared.b16 {%0,%1}, [%2];" \
                 : "=r"(r0), "=r"(r1) : "r"(addr))

#define MMA(C, A0, A1, A2, A3, B0, B1) \
    asm volatile("mma.sync.aligned.m16n8k16.row.col.f32.bf16.bf16.f32 " \
                 "{%0,%1,%2,%3}, {%4,%5,%6,%7}, {%8,%9}, {%0,%1,%2,%3};" \
                 : "+f"(C[0]), "+f"(C[1]), "+f"(C[2]), "+f"(C[3]) \
                 : "r"(A0), "r"(A1), "r"(A2), "r"(A3), "r"(B0), "r"(B1))

__global__ __launch_bounds__(NTHREADS, 4) void lrp_main_kernel(
    const float* __restrict__ nfeat,
    const void*  __restrict__ efeat_idx,
    const void*  __restrict__ n_row_probe,
    const void*  __restrict__ n_col, const float* __restrict__ n_val,
    const void*  __restrict__ e_col, const float* __restrict__ e_val,
    const void*  __restrict__ p_row, const float* __restrict__ p_val,
    const float* __restrict__ bias,
    const float* __restrict__ bond_emb,
    float* __restrict__ out)
{
    extern __shared__ __align__(128) char smem[];
    const uint32_t sbase = smem_u32(smem);

    const int tid   = threadIdx.x;
    const int wid   = tid >> 5;
    const int lane  = tid & 31;
    const int pbase = blockIdx.x * PPB;
    const bool i64  = (((const int*)n_row_probe)[1] == 0);

    // ---- stage B: linear copy of precomputed 16KB image (conflict-free)
    {
        const uint4* src = (const uint4*)g_Bpack;
        uint4* dst = (uint4*)(smem + OFF_BH);
        #pragma unroll
        for (int i = tid; i < 1024; i += NTHREADS) dst[i] = src[i];
    }
    if (tid < 64) ((float*)(smem + OFF_EMB))[tid]  = bond_emb[tid];
    if (tid < 16) ((float*)(smem + OFF_BIAS))[tid] = bias[tid];

    // ---- stage 2048 m-row records {nc, t, nv, ev}, column-swizzled
    const long long mhalf = (long long)pbase * 8;
    #pragma unroll 1
    for (int it = 0; it < 4; ++it) {
        int i  = it * NTHREADS + tid;   // pair idx 0..1023
        int pl = i >> 3;                // p-local 0..127
        int l2 = (i << 1) & 15;         // even l
        float4 rec0, rec1;
        if (pbase + pl < PP) {
            long long nc0, nc1, ec0, ec1;
            if (i64) {
                longlong2 ncp = ((const longlong2*)n_col)[mhalf + i];
                longlong2 ecp = ((const longlong2*)e_col)[mhalf + i];
                nc0 = ncp.x; nc1 = ncp.y; ec0 = ecp.x; ec1 = ecp.y;
            } else {
                int2 ncp = ((const int2*)n_col)[mhalf + i];
                int2 ecp = ((const int2*)e_col)[mhalf + i];
                nc0 = ncp.x; nc1 = ncp.y; ec0 = ecp.x; ec1 = ecp.y;
            }
            int t0 = i64 ? (int)((const long long*)efeat_idx)[ec0]
                         : ((const int*)efeat_idx)[(int)ec0];
            int t1 = i64 ? (int)((const long long*)efeat_idx)[ec1]
                         : ((const int*)efeat_idx)[(int)ec1];
            float2 nvp = ((const float2*)n_val)[mhalf + i];
            float2 evp = ((const float2*)e_val)[mhalf + i];
            rec0 = make_float4(__int_as_float((int)nc0), __int_as_float(t0), nvp.x, evp.x);
            rec1 = make_float4(__int_as_float((int)nc1), __int_as_float(t1), nvp.y, evp.y);
        } else {
            rec0 = make_float4(0.f, 0.f, 0.f, 0.f);
            rec1 = rec0;
        }
        int ph0 = (pl & ~7) | ((pl + l2) & 7);
        int ph1 = (pl & ~7) | ((pl + l2 + 1) & 7);
        *(float4*)(smem + OFF_REC + l2 * 2048 + ph0 * 16)       = rec0;
        *(float4*)(smem + OFF_REC + (l2 + 1) * 2048 + ph1 * 16) = rec1;
    }
    __syncthreads();

    // ---- per-warp mma mainloop: warp owns rows [16*wid, 16*wid+16)
    const int g = lane >> 2;        // 0..7
    const int j = lane & 3;         // k-piece: d in {4j..4j+3}
    const int row0 = 16 * wid + g;  // local rows row0, row0+8
    const float4* nf4 = (const float4*)nfeat;
    const float4* eb4 = (const float4*)(smem + OFF_EMB);

    float D0[4] = {0.f, 0.f, 0.f, 0.f};
    float D1[4] = {0.f, 0.f, 0.f, 0.f};

    float4 cx[2]; float cnv[2], cev[2]; int ct[2];
    // prologue: recs + gathers for l = 0
    #pragma unroll
    for (int r = 0; r < 2; ++r) {
        int row = row0 + 8 * r;
        int phys = (row & ~7) | (row & 7);  // l=0
        float4 rec = *(const float4*)(smem + OFF_REC + phys * 16);
        int nc = __float_as_int(rec.x);
        ct[r] = __float_as_int(rec.y); cnv[r] = rec.z; cev[r] = rec.w;
        cx[r] = __ldg(nf4 + (long long)nc * 4 + j);
    }

    const uint32_t baddr_h = sbase + OFF_BH + ((lane >> 3) & 1) * 256 + (lane & 7) * 16;
    const uint32_t baddr_l = sbase + OFF_BL + ((lane >> 3) & 1) * 256 + (lane & 7) * 16;

    #pragma unroll 1
    for (int l = 0; l < 16; ++l) {
        // ---- build A frags (hi/lo): d {4j..4j+3} contiguous
        uint32_t ah[4], al[4];
        #pragma unroll
        for (int r = 0; r < 2; ++r) {
            float4 e = eb4[ct[r] * 4 + j];
            float x0 = fmaf(cnv[r], cx[r].x, cev[r] * e.x);
            float x1 = fmaf(cnv[r], cx[r].y, cev[r] * e.y);
            float x2 = fmaf(cnv[r], cx[r].z, cev[r] * e.z);
            float x3 = fmaf(cnv[r], cx[r].w, cev[r] * e.w);
            uint32_t h01, h23;
            asm("cvt.rn.bf16x2.f32 %0, %1, %2;" : "=r"(h01) : "f"(x1), "f"(x0));
            asm("cvt.rn.bf16x2.f32 %0, %1, %2;" : "=r"(h23) : "f"(x3), "f"(x2));
            float y0 = x0 - __uint_as_float(h01 << 16);
            float y1 = x1 - __uint_as_float(h01 & 0xFFFF0000u);
            float y2 = x2 - __uint_as_float(h23 << 16);
            float y3 = x3 - __uint_as_float(h23 & 0xFFFF0000u);
            uint32_t q01, q23;
            asm("cvt.rn.bf16x2.f32 %0, %1, %2;" : "=r"(q01) : "f"(y1), "f"(y0));
            asm("cvt.rn.bf16x2.f32 %0, %1, %2;" : "=r"(q23) : "f"(y3), "f"(y2));
            ah[r] = h01; ah[2 + r] = h23;
            al[r] = q01; al[2 + r] = q23;
        }
        // ---- prefetch next l's recs + gathers
        if (l < 15) {
            #pragma unroll
            for (int r = 0; r < 2; ++r) {
                int row = row0 + 8 * r;
                int phys = (row & ~7) | ((row + l + 1) & 7);
                float4 rec = *(const float4*)(smem + OFF_REC + (l + 1) * 2048 + phys * 16);
                int nc = __float_as_int(rec.x);
                ct[r] = __float_as_int(rec.y); cnv[r] = rec.z; cev[r] = rec.w;
                cx[r] = __ldg(nf4 + (long long)nc * 4 + j);
            }
        }
        // ---- B frags for this l (W^T hi/lo, two n8 tiles)
        uint32_t bh0a, bh0b, bh1a, bh1b, bl0a, bl0b, bl1a, bl1b;
        LDMX2(bh0a, bh0b, baddr_h + l * 512);
        LDMX2(bh1a, bh1b, baddr_h + l * 512 + 128);
        LDMX2(bl0a, bl0b, baddr_l + l * 512);
        LDMX2(bl1a, bl1b, baddr_l + l * 512 + 128);
        // ---- 6 mma: Ah*Bh + Ah*Bl + Al*Bh, both n-tiles
        MMA(D0, ah[0], ah[1], ah[2], ah[3], bh0a, bh0b);
        MMA(D0, ah[0], ah[1], ah[2], ah[3], bl0a, bl0b);
        MMA(D0, al[0], al[1], al[2], al[3], bh0a, bh0b);
        MMA(D1, ah[0], ah[1], ah[2], ah[3], bh1a, bh1b);
        MMA(D1, ah[0], ah[1], ah[2], ah[3], bl1a, bl1b);
        MMA(D1, al[0], al[1], al[2], al[3], bh1a, bh1b);
    }

    // ---- epilogue: lane holds rows row0, row0+8; cols 2j,2j+1 (+8 for D1)
    const float* sBias = (const float*)(smem + OFF_BIAS);
    const int c0 = 2 * j;
    #pragma unroll
    for (int r = 0; r < 2; ++r) {
        int p = pbase + row0 + 8 * r;
        if (p >= PP) continue;
        long long pr = i64 ? ((const long long*)p_row)[p]
                           : (long long)((const int*)p_row)[p];
        float pv = p_val[p];
        float2 fdA = *(const float2*)(g_fd + pr * 16 + c0);
        float2 fdB = *(const float2*)(g_fd + pr * 16 + 8 + c0);
        float vA0 = fmaxf(D0[2 * r + 0] + sBias[c0],     0.f) * pv * fdA.x;
        float vA1 = fmaxf(D0[2 * r + 1] + sBias[c0 + 1], 0.f) * pv * fdA.y;
        float vB0 = fmaxf(D1[2 * r + 0] + sBias[8 + c0],     0.f) * pv * fdB.x;
        float vB1 = fmaxf(D1[2 * r + 1] + sBias[8 + c0 + 1], 0.f) * pv * fdB.y;
        RED2(out + pr * 16 + c0, vA0, vA1);
        RED2(out + pr * 16 + 8 + c0, vB0, vB1);
    }
}

extern "C" void kernel_launch(void* const* d_in, const int* in_sizes, int n_in,
                              void* d_out, int out_size)
{
    const float* nfeat     = (const float*)d_in[0];
    const void*  efeat_idx = d_in[1];
    const void*  n_row     = d_in[2];
    const void*  n_col     = d_in[3];
    const float* n_val     = (const float*)d_in[4];
    const void*  e_col     = d_in[6];
    const float* e_val     = (const float*)d_in[7];
    const void*  p_row     = d_in[8];
    const float* p_val     = (const float*)d_in[10];
    const float* degs      = (const float*)d_in[11];
    const float* weights   = (const float*)d_in[12];
    const float* bias      = (const float*)d_in[13];
    const float* W0        = (const float*)d_in[14];
    const float* b0        = (const float*)d_in[15];
    const float* W1        = (const float*)d_in[16];
    const float* b1        = (const float*)d_in[17];
    const float* bond_emb  = (const float*)d_in[18];
    float* out = (float*)d_out;

    fd_pre_kernel<<<(NN + 255) / 256, 256>>>(degs, W0, b0, W1, b1, out);
    b_pre_kernel<<<16, 256>>>(weights);

    cudaFuncSetAttribute(lrp_main_kernel,
                         cudaFuncAttributeMaxDynamicSharedMemorySize, SMEM_TOTAL);
    int grid = (PP + PPB - 1) / PPB;  // 1954
    lrp_main_kernel<<<grid, NTHREADS, SMEM_TOTAL>>>(
        nfeat, efeat_idx, n_row, n_col, n_val, e_col, e_val,
        p_row, p_val, bias, bond_emb, out);
}